// round 9
// baseline (speedup 1.0000x reference)
#include <cuda_runtime.h>
#include <math.h>
#include <stdint.h>

#define D      512
#define NWAY   5
#define NKPTS  17
#define BM     64
#define BN     256
#define KC     32
#define NCH    16
#define TPB    256
#define PTPB   256
#define HS     260
#define NQTILES 1024

// ---- GEMM smem ----
#define SM_A      0                // 2 x 8192
#define SM_B      16384            // 2 x 32768
#define SM_TOTAL  81920

// ---- preQ smem ----
#define PQ_IMG    0                // 131072 (16 chunks x 8192)
#define PQ_PROTO  131072           // 5*512 f = 10240
#define PQ_PN     141312           // 8 f
#define PQ_DIST   141344           // 64*5 f = 1280
#define PQ_CLS    142624           // 64 f
#define PQ_TOTAL  142880

// ---- device scratch (allocation-free rule) ----
__device__ float   g_h1[25 * D];
__device__ float   g_proto[NWAY * D];
__device__ uint8_t g_W[2][NCH][32768];            // B: tf32 ldmatrix-block image
__device__ uint8_t g_Qimg[NQTILES][NCH][8192];    // A: tf32 ldmatrix-block image

// ---------------- helpers ----------------
__device__ __forceinline__ uint32_t smem_u32(const void* p) {
    uint32_t a;
    asm("{ .reg .u64 t; cvta.to.shared.u64 t, %1; cvt.u32.u64 %0, t; }" : "=r"(a) : "l"(p));
    return a;
}
__device__ __forceinline__ uint32_t f2tf32(float f) {
    uint32_t r; asm("cvt.rna.tf32.f32 %0, %1;" : "=r"(r) : "f"(f)); return r;
}
__device__ __forceinline__ void cpa16(void* dst, const void* src) {
    uint32_t d = (uint32_t)__cvta_generic_to_shared(dst);
    asm volatile("cp.async.cg.shared.global [%0], [%1], 16;" :: "r"(d), "l"(src));
}
__device__ __forceinline__ void cp_commit() { asm volatile("cp.async.commit_group;"); }
__device__ __forceinline__ void cp_wait0()  { asm volatile("cp.async.wait_group 0;"); }

__device__ __forceinline__ void ldsm4(uint32_t* r, uint32_t addr) {
    asm volatile("ldmatrix.sync.aligned.m8n8.x4.shared.b16 {%0,%1,%2,%3}, [%4];"
        : "=r"(r[0]), "=r"(r[1]), "=r"(r[2]), "=r"(r[3]) : "r"(addr));
}
__device__ __forceinline__ void mma_tf32(float* d, const uint32_t* a, const uint32_t* b) {
    asm volatile("mma.sync.aligned.m16n8k8.row.col.f32.tf32.tf32.f32 "
        "{%0,%1,%2,%3},{%4,%5,%6,%7},{%8,%9},{%0,%1,%2,%3};"
        : "+f"(d[0]), "+f"(d[1]), "+f"(d[2]), "+f"(d[3])
        : "r"(a[0]), "r"(a[1]), "r"(a[2]), "r"(a[3]), "r"(b[0]), "r"(b[1]));
}

// ---------------- weight pre-convert (B image, KC=32 chunks) ----------------
// Per (y, chunk): blk = ks*64 + noct*2 + khalf, 128B = 8 n-rows x 16B k-quad. ks 0..3.
__global__ void convW(const float* __restrict__ Wo1, const float* __restrict__ Wc1) {
    int k = blockIdx.x;           // 0..511
    int n = threadIdx.x;          // 0..511
    int y = n >> 8, nn = n & 255;
    float v = y ? Wc1[k * BN + nn] : Wo1[k * BN + nn];
    uint32_t t = f2tf32(v);
    int c = k >> 5, kin = k & 31;
    int ks = kin >> 3, kq = kin & 7, kh = kq >> 2, kp = kq & 3;
    int noct = nn >> 3, r = nn & 7;
    uint32_t off = (uint32_t)(ks * 64 + noct * 2 + kh) * 128 + r * 16 + kp * 4;
    *(uint32_t*)&g_W[y][c][off] = t;
}

// ---------------- prototype path ----------------
__global__ void proto1(const float* __restrict__ sf,
                       const float* __restrict__ W1,
                       const float* __restrict__ b1) {
    int s = blockIdx.x;
    int j = blockIdx.y * 64 + (threadIdx.x & 63);
    int kg = threadIdx.x >> 6;
    const float* srow = sf + s * D;
    float acc = 0.f;
    int k0 = kg * 128;
    #pragma unroll 8
    for (int k = k0; k < k0 + 128; k++)
        acc += srow[k] * W1[k * D + j];
    __shared__ float red[PTPB];
    red[threadIdx.x] = acc;
    __syncthreads();
    if (threadIdx.x < 64) {
        float v = red[threadIdx.x] + red[threadIdx.x + 64] + red[threadIdx.x + 128]
                + red[threadIdx.x + 192] + b1[j];
        g_h1[s * D + j] = fmaxf(v, 0.f);
    }
}

__global__ void proto2(const float* __restrict__ W2,
                       const float* __restrict__ b2,
                       float* __restrict__ proto_out) {
    int w = blockIdx.x;
    __shared__ float hsum[D];
    int t = threadIdx.x;
    for (int k = t; k < D; k += PTPB) {
        float a = 0.f;
        #pragma unroll
        for (int s = 0; s < 5; s++) a += g_h1[(w * 5 + s) * D + k];
        hsum[k] = a;
    }
    __syncthreads();
    int j = blockIdx.y * 64 + (t & 63);
    int kg = t >> 6;
    float acc = 0.f;
    int k0 = kg * 128;
    #pragma unroll 8
    for (int k = k0; k < k0 + 128; k++)
        acc += hsum[k] * W2[k * D + j];
    __shared__ float red[PTPB];
    red[t] = acc;
    __syncthreads();
    if (t < 64) {
        float p = (red[t] + red[t + 64] + red[t + 128] + red[t + 192]) * 0.2f + b2[j];
        g_proto[w * D + j] = p;
        #pragma unroll
        for (int kp = 0; kp < NKPTS; kp++)
            proto_out[(size_t)(w * NKPTS + kp) * D + j] = p;
    }
}

// ---------------- preQ: Q -> tf32 image (smem-staged, coalesced out) + distances ----------------
__global__ void __launch_bounds__(PTPB, 1)
preQ(const float* __restrict__ Q, const float* __restrict__ temp,
     float* __restrict__ dist_out, float* __restrict__ cls_out) {
    extern __shared__ char qsm[];
    float* sproto = (float*)(qsm + PQ_PROTO);
    float* spn    = (float*)(qsm + PQ_PN);
    float* sdist  = (float*)(qsm + PQ_DIST);
    float* scls   = (float*)(qsm + PQ_CLS);

    const int tid  = threadIdx.x;
    const int warp = tid >> 5;
    const int lane = tid & 31;
    const size_t q0 = (size_t)blockIdx.x * BM;

    for (int i = tid; i < NWAY * D; i += PTPB) sproto[i] = g_proto[i];
    __syncthreads();

    if (warp < NWAY) {
        float s = 0.f;
        for (int k = lane; k < D; k += 32) { float v = sproto[warp * D + k]; s += v * v; }
        #pragma unroll
        for (int off = 16; off > 0; off >>= 1) s += __shfl_xor_sync(0xffffffffu, s, off);
        if (lane == 0) spn[warp] = sqrtf(s);
    }

    const int rl = tid >> 2;       // 0..63
    const int kq = tid & 3;        // 128 k each
    const float* qr = Q + (q0 + rl) * D + kq * 128;

    float qq = 0.f, s0 = 0.f, s1 = 0.f, s2 = 0.f, s3 = 0.f, s4 = 0.f;
    const int mblk = (rl >> 4) * 4 + ((rl >> 3) & 1);   // mtile*4 + moct
    const int roff = (rl & 7) * 16;

    #pragma unroll 8
    for (int i = 0; i < 32; i++) {
        float4 v = ((const float4*)qr)[i];
        int k = kq * 128 + i * 4;
        {
            float4 p0 = *(const float4*)(sproto + 0 * D + k);
            float4 p1 = *(const float4*)(sproto + 1 * D + k);
            float4 p2 = *(const float4*)(sproto + 2 * D + k);
            float4 p3 = *(const float4*)(sproto + 3 * D + k);
            float4 p4 = *(const float4*)(sproto + 4 * D + k);
            qq += v.x * v.x + v.y * v.y + v.z * v.z + v.w * v.w;
            s0 += v.x * p0.x + v.y * p0.y + v.z * p0.z + v.w * p0.w;
            s1 += v.x * p1.x + v.y * p1.y + v.z * p1.z + v.w * p1.w;
            s2 += v.x * p2.x + v.y * p2.y + v.z * p2.z + v.w * p2.w;
            s3 += v.x * p3.x + v.y * p3.y + v.z * p3.z + v.w * p3.w;
            s4 += v.x * p4.x + v.y * p4.y + v.z * p4.z + v.w * p4.w;
        }
        // image write into SMEM (KC=32 chunks): blk = ks*16 + mtile*4 + kh*2 + moct
        int c  = k >> 5, kk = k & 31;
        int ks = kk >> 3, kh = (kk >> 2) & 1;
        uint32_t off = (uint32_t)c * 8192u
                     + (uint32_t)(ks * 16 + kh * 2 + mblk) * 128u + roff;
        *(uint4*)(qsm + PQ_IMG + off) =
            make_uint4(f2tf32(v.x), f2tf32(v.y), f2tf32(v.z), f2tf32(v.w));
    }

    #pragma unroll
    for (int off = 1; off <= 2; off <<= 1) {
        qq += __shfl_xor_sync(0xffffffffu, qq, off);
        s0 += __shfl_xor_sync(0xffffffffu, s0, off);
        s1 += __shfl_xor_sync(0xffffffffu, s1, off);
        s2 += __shfl_xor_sync(0xffffffffu, s2, off);
        s3 += __shfl_xor_sync(0xffffffffu, s3, off);
        s4 += __shfl_xor_sync(0xffffffffu, s4, off);
    }
    if (kq == 0) {
        const float T = *temp;
        float qn = sqrtf(qq);
        float sv[5] = {s0, s1, s2, s3, s4};
        float best = 3.402823e38f; int bi = 0;
        #pragma unroll
        for (int w = 0; w < NWAY; w++) {
            float denom = fmaxf(qn * spn[w], 1e-8f);
            float dv = (1.0f - sv[w] / denom) / T;
            sdist[rl * NWAY + w] = dv;
            if (dv < best) { best = dv; bi = w; }
        }
        scls[rl] = (float)bi;
    }
    __syncthreads();

    // coalesced image write-out: 131072B = 8192 uint4
    {
        const uint4* s4 = (const uint4*)(qsm + PQ_IMG);
        uint4* d4 = (uint4*)&g_Qimg[blockIdx.x][0][0];
        #pragma unroll
        for (int i = 0; i < 32; i++)
            d4[tid + i * PTPB] = s4[tid + i * PTPB];
    }

    // distance outputs (warp handles 8 rows)
    for (int rr = 0; rr < 8; rr++) {
        int r = warp * 8 + rr;
        size_t qi = q0 + r;
        for (int l = lane; l < NWAY * NKPTS; l += 32)
            dist_out[qi * (NWAY * NKPTS) + l] = sdist[r * NWAY + l / NKPTS];
        if (lane == 0) cls_out[qi] = scls[r];
    }
}

// ---------------- main GEMM kernel (2 CTAs/SM, pure LDSM+MMA) ----------------
__global__ void __launch_bounds__(TPB, 2)
query_kernel(const float* __restrict__ IC,
             const float* __restrict__ bo1, const float* __restrict__ Wo2,
             const float* __restrict__ bo2,
             const float* __restrict__ bc1, const float* __restrict__ Wc2,
             const float* __restrict__ bc2,
             float* __restrict__ kp_out, float* __restrict__ conf_out) {
    extern __shared__ char smem[];
    const uint32_t sb = smem_u32(smem);

    const int tid  = threadIdx.x;
    const int warp = tid >> 5;
    const int lane = tid & 31;
    const int g    = lane >> 2;
    const int qd   = lane & 3;
    const int y    = blockIdx.y;
    const size_t q0 = (size_t)blockIdx.x * BM;

    const uint8_t* Asrc = &g_Qimg[blockIdx.x][0][0];

    auto cpA = [&](int c, int buf) {
        const uint8_t* src = Asrc + c * 8192;
        char* dst = smem + SM_A + buf * 8192;
        #pragma unroll
        for (int i = 0; i < 2; i++) {
            int idx = (tid + i * TPB) * 16;
            cpa16(dst + idx, src + idx);
        }
    };
    auto cpB = [&](int c, int buf) {
        const uint8_t* src = &g_W[y][c][0];
        char* dst = smem + SM_B + buf * 32768;
        #pragma unroll
        for (int i = 0; i < 8; i++)
            cpa16(dst + tid * 128 + i * 16, src + tid * 128 + i * 16);
    };

    cpA(0, 0);
    cpB(0, 0);
    cp_commit();
    cp_wait0();
    __syncthreads();

    float acc[2][8][4];
    #pragma unroll
    for (int mi = 0; mi < 2; mi++)
        #pragma unroll
        for (int ni = 0; ni < 8; ni++)
            #pragma unroll
            for (int i = 0; i < 4; i++) acc[mi][ni][i] = 0.f;

    const int wm = (warp & 1) * 32;            // 2 m-groups of 32
    const int wn = (warp >> 1) * 64;           // 4 n-groups of 64
    const uint32_t a_mt = (uint32_t)((warp & 1) * 2);
    const uint32_t b_blk0 = (uint32_t)(wn >> 2);

    #pragma unroll 1
    for (int c = 0; c < NCH; c++) {
        int buf = c & 1;
        if (c < NCH - 1) {
            cpA(c + 1, buf ^ 1);
            cpB(c + 1, buf ^ 1);
            cp_commit();
        }

        uint32_t ab   = sb + SM_A + buf * 8192;
        uint32_t bbuf = sb + SM_B + buf * 32768;
        #pragma unroll
        for (int ks = 0; ks < 4; ks++) {
            uint32_t A0[4], A1[4];
            ldsm4(A0, ab + (uint32_t)(ks * 16 + (a_mt + 0) * 4) * 128 + lane * 16);
            ldsm4(A1, ab + (uint32_t)(ks * 16 + (a_mt + 1) * 4) * 128 + lane * 16);
            #pragma unroll
            for (int p = 0; p < 4; p++) {
                uint32_t r[4];
                ldsm4(r, bbuf + (uint32_t)(ks * 64 + b_blk0 + 4 * p) * 128 + lane * 16);
                mma_tf32(acc[0][2 * p],     A0, r);
                mma_tf32(acc[0][2 * p + 1], A0, r + 2);
                mma_tf32(acc[1][2 * p],     A1, r);
                mma_tf32(acc[1][2 * p + 1], A1, r + 2);
            }
        }

        if (c < NCH - 1) {
            cp_wait0();
            __syncthreads();
        }
    }
    __syncthreads();   // all smem reads done before H reuse

    // store H = relu(acc + bias)
    {
        const float* bb1 = y ? bc1 : bo1;
        float* Hs = (float*)smem;
        #pragma unroll
        for (int ni = 0; ni < 8; ni++) {
            int colb = wn + ni * 8 + 2 * qd;
            float b0v = bb1[colb], b1v = bb1[colb + 1];
            #pragma unroll
            for (int mi = 0; mi < 2; mi++) {
                int r0 = wm + mi * 16 + g;
                Hs[r0 * HS + colb]           = fmaxf(acc[mi][ni][0] + b0v, 0.f);
                Hs[r0 * HS + colb + 1]       = fmaxf(acc[mi][ni][1] + b1v, 0.f);
                Hs[(r0 + 8) * HS + colb]     = fmaxf(acc[mi][ni][2] + b0v, 0.f);
                Hs[(r0 + 8) * HS + colb + 1] = fmaxf(acc[mi][ni][3] + b1v, 0.f);
            }
        }
    }
    __syncthreads();

    // heads + outputs (warp handles 8 rows)
    const float* Hs = (const float*)smem;
    if (y == 0) {
        for (int rr = 0; rr < 8; rr++) {
            int r = warp * 8 + rr;
            size_t qi = q0 + r;
            float ox = 0.f, oy = 0.f;
            for (int i = lane; i < BN; i += 32) {
                float h = Hs[r * HS + i];
                ox += h * Wo2[2 * i];
                oy += h * Wo2[2 * i + 1];
            }
            #pragma unroll
            for (int off = 16; off > 0; off >>= 1) {
                ox += __shfl_xor_sync(0xffffffffu, ox, off);
                oy += __shfl_xor_sync(0xffffffffu, oy, off);
            }
            float kx = 0.f, ky = 0.f;
            if (lane == 0) {
                ox += bo2[0]; oy += bo2[1];
                kx = IC[qi * 2 + 0] / (1.0f + expf(-ox));
                ky = IC[qi * 2 + 1] / (1.0f + expf(-oy));
            }
            kx = __shfl_sync(0xffffffffu, kx, 0);
            ky = __shfl_sync(0xffffffffu, ky, 0);
            for (int l = lane; l < 2 * NKPTS; l += 32)
                kp_out[qi * (2 * NKPTS) + l] = (l & 1) ? ky : kx;
        }
    } else {
        for (int rr = 0; rr < 8; rr++) {
            int r = warp * 8 + rr;
            size_t qi = q0 + r;
            float cl = 0.f;
            for (int i = lane; i < BN; i += 32)
                cl += Hs[r * HS + i] * Wc2[i];
            #pragma unroll
            for (int off = 16; off > 0; off >>= 1)
                cl += __shfl_xor_sync(0xffffffffu, cl, off);
            float cf = 0.f;
            if (lane == 0)
                cf = 1.0f / (1.0f + expf(-(cl + bc2[0])));
            cf = __shfl_sync(0xffffffffu, cf, 0);
            if (lane < NKPTS)
                conf_out[qi * NKPTS + lane] = cf;
        }
    }
}

extern "C" void kernel_launch(void* const* d_in, const int* in_sizes, int n_in,
                              void* d_out, int out_size) {
    const float* sf   = (const float*)d_in[0];
    const float* Q    = (const float*)d_in[2];
    const float* IC   = (const float*)d_in[3];
    const float* W1   = (const float*)d_in[4];
    const float* b1   = (const float*)d_in[5];
    const float* W2   = (const float*)d_in[6];
    const float* b2   = (const float*)d_in[7];
    const float* Wo1  = (const float*)d_in[8];
    const float* bo1  = (const float*)d_in[9];
    const float* Wo2  = (const float*)d_in[10];
    const float* bo2  = (const float*)d_in[11];
    const float* Wc1  = (const float*)d_in[12];
    const float* bc1  = (const float*)d_in[13];
    const float* Wc2  = (const float*)d_in[14];
    const float* bc2  = (const float*)d_in[15];
    const float* temp = (const float*)d_in[16];

    const int nq = in_sizes[2] / D;

    float* out       = (float*)d_out;
    float* kp_out    = out;
    float* conf_out  = kp_out   + (size_t)nq * 2 * NKPTS;
    float* dist_out  = conf_out + (size_t)nq * NKPTS;
    float* cls_out   = dist_out + (size_t)nq * NWAY * NKPTS;
    float* proto_out = cls_out  + (size_t)nq;

    convW<<<D, 512>>>(Wo1, Wc1);
    proto1<<<dim3(25, 8), PTPB>>>(sf, W1, b1);
    proto2<<<dim3(NWAY, 8), PTPB>>>(W2, b2, proto_out);

    cudaFuncSetAttribute((const void*)preQ,
                         cudaFuncAttributeMaxDynamicSharedMemorySize, PQ_TOTAL);
    preQ<<<nq / BM, PTPB, PQ_TOTAL>>>(Q, temp, dist_out, cls_out);

    cudaFuncSetAttribute((const void*)query_kernel,
                         cudaFuncAttributeMaxDynamicSharedMemorySize, SM_TOTAL);
    query_kernel<<<dim3(nq / BM, 2), TPB, SM_TOTAL>>>(
        IC, bo1, Wo2, bo2, bc1, Wc2, bc2, kp_out, conf_out);
}

// round 10
// speedup vs baseline: 1.7818x; 1.7818x over previous
#include <cuda_runtime.h>
#include <math.h>
#include <stdint.h>

#define D      512
#define NWAY   5
#define NKPTS  17
#define BM     128
#define BN     256
#define KC     64
#define NCH    8
#define TPB    256
#define PTPB   256
#define HS     260
#define NQTILES 512

// ---- GEMM smem ----
#define SM_A      0                // 2 x 32768
#define SM_B      65536            // 2 x 65536
#define SM_TOTAL  196608

// ---- device scratch (allocation-free rule) ----
__device__ float   g_h1[25 * D];
__device__ float   g_proto[NWAY * D];
__device__ uint8_t g_W[2][NCH][65536];            // B: tf32 ldmatrix-block image
__device__ uint8_t g_Qimg[NQTILES][NCH][32768];   // A: tf32 ldmatrix-block image

// ---------------- helpers ----------------
__device__ __forceinline__ uint32_t smem_u32(const void* p) {
    uint32_t a;
    asm("{ .reg .u64 t; cvta.to.shared.u64 t, %1; cvt.u32.u64 %0, t; }" : "=r"(a) : "l"(p));
    return a;
}
__device__ __forceinline__ uint32_t f2tf32(float f) {
    uint32_t r; asm("cvt.rna.tf32.f32 %0, %1;" : "=r"(r) : "f"(f)); return r;
}
__device__ __forceinline__ void cpa16(void* dst, const void* src) {
    uint32_t d = (uint32_t)__cvta_generic_to_shared(dst);
    asm volatile("cp.async.cg.shared.global [%0], [%1], 16;" :: "r"(d), "l"(src));
}
__device__ __forceinline__ void cp_commit() { asm volatile("cp.async.commit_group;"); }
__device__ __forceinline__ void cp_wait0()  { asm volatile("cp.async.wait_group 0;"); }

__device__ __forceinline__ void ldsm4(uint32_t* r, uint32_t addr) {
    asm volatile("ldmatrix.sync.aligned.m8n8.x4.shared.b16 {%0,%1,%2,%3}, [%4];"
        : "=r"(r[0]), "=r"(r[1]), "=r"(r[2]), "=r"(r[3]) : "r"(addr));
}
__device__ __forceinline__ void mma_tf32(float* d, const uint32_t* a, const uint32_t* b) {
    asm volatile("mma.sync.aligned.m16n8k8.row.col.f32.tf32.tf32.f32 "
        "{%0,%1,%2,%3},{%4,%5,%6,%7},{%8,%9},{%0,%1,%2,%3};"
        : "+f"(d[0]), "+f"(d[1]), "+f"(d[2]), "+f"(d[3])
        : "r"(a[0]), "r"(a[1]), "r"(a[2]), "r"(a[3]), "r"(b[0]), "r"(b[1]));
}

// ---------------- weight pre-convert (B image, KC=64) ----------------
// Per (y, chunk): blk = ks*64 + noct*2 + khalf, 128B = 8 n-rows x 16B k-quad.
__global__ void convW(const float* __restrict__ Wo1, const float* __restrict__ Wc1) {
    int k = blockIdx.x;           // 0..511
    int n = threadIdx.x;          // 0..511
    int y = n >> 8, nn = n & 255;
    float v = y ? Wc1[k * BN + nn] : Wo1[k * BN + nn];
    uint32_t t = f2tf32(v);
    int c = k >> 6, kin = k & 63;
    int ks = kin >> 3, kq = kin & 7, kh = kq >> 2, kp = kq & 3;
    int noct = nn >> 3, r = nn & 7;
    uint32_t off = (uint32_t)(ks * 64 + noct * 2 + kh) * 128 + r * 16 + kp * 4;
    *(uint32_t*)&g_W[y][c][off] = t;
}

// ---------------- prototype path ----------------
__global__ void proto1(const float* __restrict__ sf,
                       const float* __restrict__ W1,
                       const float* __restrict__ b1) {
    int s = blockIdx.x;
    int j = blockIdx.y * 64 + (threadIdx.x & 63);
    int kg = threadIdx.x >> 6;
    const float* srow = sf + s * D;
    float acc = 0.f;
    int k0 = kg * 128;
    #pragma unroll 8
    for (int k = k0; k < k0 + 128; k++)
        acc += srow[k] * W1[k * D + j];
    __shared__ float red[PTPB];
    red[threadIdx.x] = acc;
    __syncthreads();
    if (threadIdx.x < 64) {
        float v = red[threadIdx.x] + red[threadIdx.x + 64] + red[threadIdx.x + 128]
                + red[threadIdx.x + 192] + b1[j];
        g_h1[s * D + j] = fmaxf(v, 0.f);
    }
}

__global__ void proto2(const float* __restrict__ W2,
                       const float* __restrict__ b2,
                       float* __restrict__ proto_out) {
    int w = blockIdx.x;
    __shared__ float hsum[D];
    int t = threadIdx.x;
    for (int k = t; k < D; k += PTPB) {
        float a = 0.f;
        #pragma unroll
        for (int s = 0; s < 5; s++) a += g_h1[(w * 5 + s) * D + k];
        hsum[k] = a;
    }
    __syncthreads();
    int j = blockIdx.y * 64 + (t & 63);
    int kg = t >> 6;
    float acc = 0.f;
    int k0 = kg * 128;
    #pragma unroll 8
    for (int k = k0; k < k0 + 128; k++)
        acc += hsum[k] * W2[k * D + j];
    __shared__ float red[PTPB];
    red[t] = acc;
    __syncthreads();
    if (t < 64) {
        float p = (red[t] + red[t + 64] + red[t + 128] + red[t + 192]) * 0.2f + b2[j];
        g_proto[w * D + j] = p;
        #pragma unroll
        for (int kp = 0; kp < NKPTS; kp++)
            proto_out[(size_t)(w * NKPTS + kp) * D + j] = p;
    }
}

// ---------------- preQ: sector-optimal transform + exact distances ----------------
// Warp = 8 consecutive rows x 4 k-quads. Each LDG.128 = 8x64B segs; each STG.128
// writes 4 full 128B lines of the image.
__global__ void __launch_bounds__(PTPB, 2)
preQ(const float* __restrict__ Q, const float* __restrict__ temp,
     float* __restrict__ dist_out, float* __restrict__ cls_out) {
    __shared__ float sproto[NWAY * D];
    __shared__ float spn[NWAY];
    __shared__ float sdist[BM * NWAY];
    __shared__ float scls[BM];

    const int tid  = threadIdx.x;
    const int warp = tid >> 5;
    const int lane = tid & 31;
    const size_t q0 = (size_t)blockIdx.x * BM;

    for (int i = tid; i < NWAY * D; i += PTPB) sproto[i] = g_proto[i];
    __syncthreads();

    if (warp < NWAY) {
        float s = 0.f;
        for (int k = lane; k < D; k += 32) { float v = sproto[warp * D + k]; s += v * v; }
        #pragma unroll
        for (int off = 16; off > 0; off >>= 1) s += __shfl_xor_sync(0xffffffffu, s, off);
        if (lane == 0) spn[warp] = sqrtf(s);
    }
    __syncthreads();

    const int rsub = lane >> 2;    // row within warp octet
    const int lq   = lane & 3;     // k-quad group
    uint8_t* img = &g_Qimg[blockIdx.x][0][0];

    #pragma unroll 1
    for (int o = 0; o < 2; o++) {
        int rowl = o * 64 + warp * 8 + rsub;       // tile-local row 0..127
        const float* qr = Q + (q0 + rowl) * D;
        const int mblk = (rowl >> 4) * 4 + ((rowl >> 3) & 1);
        const int roff = (rowl & 7) * 16;

        float qq = 0.f, s0 = 0.f, s1 = 0.f, s2 = 0.f, s3 = 0.f, s4 = 0.f;
        #pragma unroll 4
        for (int j = 0; j < 32; j++) {
            float4 v = ((const float4*)qr)[lq + j * 4];
            int k = lq * 4 + j * 16;
            {
                float4 p0 = *(const float4*)(sproto + 0 * D + k);
                float4 p1 = *(const float4*)(sproto + 1 * D + k);
                float4 p2 = *(const float4*)(sproto + 2 * D + k);
                float4 p3 = *(const float4*)(sproto + 3 * D + k);
                float4 p4 = *(const float4*)(sproto + 4 * D + k);
                qq += v.x * v.x + v.y * v.y + v.z * v.z + v.w * v.w;
                s0 += v.x * p0.x + v.y * p0.y + v.z * p0.z + v.w * p0.w;
                s1 += v.x * p1.x + v.y * p1.y + v.z * p1.z + v.w * p1.w;
                s2 += v.x * p2.x + v.y * p2.y + v.z * p2.z + v.w * p2.w;
                s3 += v.x * p3.x + v.y * p3.y + v.z * p3.z + v.w * p3.w;
                s4 += v.x * p4.x + v.y * p4.y + v.z * p4.z + v.w * p4.w;
            }
            int c  = j >> 2;
            int kk = k & 63;
            int ks = kk >> 3, kh = (kk >> 2) & 1;
            uint32_t off = (uint32_t)c * 32768u
                         + (uint32_t)(ks * 32 + kh * 2 + mblk) * 128u + roff;
            *(uint4*)(img + off) =
                make_uint4(f2tf32(v.x), f2tf32(v.y), f2tf32(v.z), f2tf32(v.w));
        }

        // reduce over the 4-lane k-group
        #pragma unroll
        for (int off = 1; off <= 2; off <<= 1) {
            qq += __shfl_xor_sync(0xffffffffu, qq, off);
            s0 += __shfl_xor_sync(0xffffffffu, s0, off);
            s1 += __shfl_xor_sync(0xffffffffu, s1, off);
            s2 += __shfl_xor_sync(0xffffffffu, s2, off);
            s3 += __shfl_xor_sync(0xffffffffu, s3, off);
            s4 += __shfl_xor_sync(0xffffffffu, s4, off);
        }
        if (lq == 0) {
            const float T = *temp;
            float qn = sqrtf(qq);
            float sv[5] = {s0, s1, s2, s3, s4};
            float best = 3.402823e38f; int bi = 0;
            #pragma unroll
            for (int w = 0; w < NWAY; w++) {
                float denom = fmaxf(qn * spn[w], 1e-8f);
                float dv = (1.0f - sv[w] / denom) / T;
                sdist[rowl * NWAY + w] = dv;
                if (dv < best) { best = dv; bi = w; }
            }
            scls[rowl] = (float)bi;
        }
    }
    __syncthreads();

    // coalesced distance outputs (warp handles 16 rows)
    for (int rr = 0; rr < 16; rr++) {
        int r = warp * 16 + rr;
        size_t qi = q0 + r;
        for (int l = lane; l < NWAY * NKPTS; l += 32)
            dist_out[qi * (NWAY * NKPTS) + l] = sdist[r * NWAY + l / NKPTS];
        if (lane == 0) cls_out[qi] = scls[r];
    }
}

// ---------------- main GEMM kernel (64x64 warp tiles, TPB=256) ----------------
__global__ void __launch_bounds__(TPB, 1)
query_kernel(const float* __restrict__ IC,
             const float* __restrict__ bo1, const float* __restrict__ Wo2,
             const float* __restrict__ bo2,
             const float* __restrict__ bc1, const float* __restrict__ Wc2,
             const float* __restrict__ bc2,
             float* __restrict__ kp_out, float* __restrict__ conf_out) {
    extern __shared__ char smem[];
    const uint32_t sb = smem_u32(smem);

    const int tid  = threadIdx.x;
    const int warp = tid >> 5;
    const int lane = tid & 31;
    const int g    = lane >> 2;
    const int qd   = lane & 3;
    const int y    = blockIdx.y;
    const size_t q0 = (size_t)blockIdx.x * BM;

    const uint8_t* Asrc = &g_Qimg[blockIdx.x][0][0];

    auto cpA = [&](int c, int buf) {
        const uint8_t* src = Asrc + c * 32768;
        char* dst = smem + SM_A + buf * 32768;
        #pragma unroll
        for (int i = 0; i < 8; i++) {
            int idx = (tid + i * TPB) * 16;
            cpa16(dst + idx, src + idx);
        }
    };
    auto cpB = [&](int c, int buf) {
        const uint8_t* src = &g_W[y][c][0];
        char* dst = smem + SM_B + buf * 65536;
        #pragma unroll
        for (int i = 0; i < 16; i++) {
            int idx = (tid + i * TPB) * 16;
            cpa16(dst + idx, src + idx);
        }
    };

    cpA(0, 0);
    cpB(0, 0);
    cp_commit();
    cp_wait0();
    __syncthreads();

    float acc[4][8][4];
    #pragma unroll
    for (int mi = 0; mi < 4; mi++)
        #pragma unroll
        for (int ni = 0; ni < 8; ni++)
            #pragma unroll
            for (int i = 0; i < 4; i++) acc[mi][ni][i] = 0.f;

    const int wm = (warp & 1) * 64;            // 2 m-groups of 64
    const int wn = (warp >> 1) * 64;           // 4 n-groups of 64
    const uint32_t a_mt0 = (uint32_t)((warp & 1) * 4);
    const uint32_t b_blk0 = (uint32_t)(wn >> 2);

    #pragma unroll 1
    for (int c = 0; c < NCH; c++) {
        int buf = c & 1;
        if (c < NCH - 1) {
            cpA(c + 1, buf ^ 1);
            cpB(c + 1, buf ^ 1);
            cp_commit();
        }

        uint32_t ab   = sb + SM_A + buf * 32768;
        uint32_t bbuf = sb + SM_B + buf * 65536;
        #pragma unroll
        for (int ks = 0; ks < 8; ks++) {
            uint32_t Af[4][4];
            #pragma unroll
            for (int j = 0; j < 4; j++)
                ldsm4(Af[j], ab + (uint32_t)(ks * 32 + (a_mt0 + j) * 4) * 128 + lane * 16);
            #pragma unroll
            for (int p = 0; p < 4; p++) {
                uint32_t r[4];
                ldsm4(r, bbuf + (uint32_t)(ks * 64 + b_blk0 + 4 * p) * 128 + lane * 16);
                #pragma unroll
                for (int j = 0; j < 4; j++) {
                    mma_tf32(acc[j][2 * p],     Af[j], r);
                    mma_tf32(acc[j][2 * p + 1], Af[j], r + 2);
                }
            }
        }

        if (c < NCH - 1) {
            cp_wait0();
            __syncthreads();
        }
    }
    __syncthreads();   // all smem reads done before H reuse

    // store H = relu(acc + bias)
    {
        const float* bb1 = y ? bc1 : bo1;
        float* Hs = (float*)smem;
        #pragma unroll
        for (int ni = 0; ni < 8; ni++) {
            int colb = wn + ni * 8 + 2 * qd;
            float b0v = bb1[colb], b1v = bb1[colb + 1];
            #pragma unroll
            for (int mi = 0; mi < 4; mi++) {
                int r0 = wm + mi * 16 + g;
                Hs[r0 * HS + colb]           = fmaxf(acc[mi][ni][0] + b0v, 0.f);
                Hs[r0 * HS + colb + 1]       = fmaxf(acc[mi][ni][1] + b1v, 0.f);
                Hs[(r0 + 8) * HS + colb]     = fmaxf(acc[mi][ni][2] + b0v, 0.f);
                Hs[(r0 + 8) * HS + colb + 1] = fmaxf(acc[mi][ni][3] + b1v, 0.f);
            }
        }
    }
    __syncthreads();

    // heads + outputs (warp handles 16 rows)
    const float* Hs = (const float*)smem;
    if (y == 0) {
        for (int rr = 0; rr < 16; rr++) {
            int r = warp * 16 + rr;
            size_t qi = q0 + r;
            float ox = 0.f, oy = 0.f;
            for (int i = lane; i < BN; i += 32) {
                float h = Hs[r * HS + i];
                ox += h * Wo2[2 * i];
                oy += h * Wo2[2 * i + 1];
            }
            #pragma unroll
            for (int off = 16; off > 0; off >>= 1) {
                ox += __shfl_xor_sync(0xffffffffu, ox, off);
                oy += __shfl_xor_sync(0xffffffffu, oy, off);
            }
            float kx = 0.f, ky = 0.f;
            if (lane == 0) {
                ox += bo2[0]; oy += bo2[1];
                kx = IC[qi * 2 + 0] / (1.0f + expf(-ox));
                ky = IC[qi * 2 + 1] / (1.0f + expf(-oy));
            }
            kx = __shfl_sync(0xffffffffu, kx, 0);
            ky = __shfl_sync(0xffffffffu, ky, 0);
            for (int l = lane; l < 2 * NKPTS; l += 32)
                kp_out[qi * (2 * NKPTS) + l] = (l & 1) ? ky : kx;
        }
    } else {
        for (int rr = 0; rr < 16; rr++) {
            int r = warp * 16 + rr;
            size_t qi = q0 + r;
            float cl = 0.f;
            for (int i = lane; i < BN; i += 32)
                cl += Hs[r * HS + i] * Wc2[i];
            #pragma unroll
            for (int off = 16; off > 0; off >>= 1)
                cl += __shfl_xor_sync(0xffffffffu, cl, off);
            float cf = 0.f;
            if (lane == 0)
                cf = 1.0f / (1.0f + expf(-(cl + bc2[0])));
            cf = __shfl_sync(0xffffffffu, cf, 0);
            if (lane < NKPTS)
                conf_out[qi * NKPTS + lane] = cf;
        }
    }
}

extern "C" void kernel_launch(void* const* d_in, const int* in_sizes, int n_in,
                              void* d_out, int out_size) {
    const float* sf   = (const float*)d_in[0];
    const float* Q    = (const float*)d_in[2];
    const float* IC   = (const float*)d_in[3];
    const float* W1   = (const float*)d_in[4];
    const float* b1   = (const float*)d_in[5];
    const float* W2   = (const float*)d_in[6];
    const float* b2   = (const float*)d_in[7];
    const float* Wo1  = (const float*)d_in[8];
    const float* bo1  = (const float*)d_in[9];
    const float* Wo2  = (const float*)d_in[10];
    const float* bo2  = (const float*)d_in[11];
    const float* Wc1  = (const float*)d_in[12];
    const float* bc1  = (const float*)d_in[13];
    const float* Wc2  = (const float*)d_in[14];
    const float* bc2  = (const float*)d_in[15];
    const float* temp = (const float*)d_in[16];

    const int nq = in_sizes[2] / D;

    float* out       = (float*)d_out;
    float* kp_out    = out;
    float* conf_out  = kp_out   + (size_t)nq * 2 * NKPTS;
    float* dist_out  = conf_out + (size_t)nq * NKPTS;
    float* cls_out   = dist_out + (size_t)nq * NWAY * NKPTS;
    float* proto_out = cls_out  + (size_t)nq;

    convW<<<D, 512>>>(Wo1, Wc1);
    proto1<<<dim3(25, 8), PTPB>>>(sf, W1, b1);
    proto2<<<dim3(NWAY, 8), PTPB>>>(W2, b2, proto_out);

    preQ<<<nq / BM, PTPB>>>(Q, temp, dist_out, cls_out);

    cudaFuncSetAttribute((const void*)query_kernel,
                         cudaFuncAttributeMaxDynamicSharedMemorySize, SM_TOTAL);
    query_kernel<<<dim3(nq / BM, 2), TPB, SM_TOTAL>>>(
        IC, bo1, Wo2, bo2, bc1, Wc2, bc2, kp_out, conf_out);
}